// round 13
// baseline (speedup 1.0000x reference)
#include <cuda_runtime.h>
#include <cuda_fp16.h>
#include <stdint.h>

// W4A16 grouped-dequant GEMM:  out[32, 28672] = x[32, 8192] @ dequant(qweight) + bias
// All fp16 tensors are promoted to float32 by the harness (x, scales, bias, out).
//
// R12 = R10's shape (NTILE=128, 4 warps, regs-lean) + R11's weight smem staging
// (measured 4x per-work L1 cut) -> 32KB smem/block, 7 blocks/SM, 44% occupancy,
// single wave at KSPLIT=4. Fused split-K reduction (counter + last-block sum).

namespace {

constexpr int M       = 32;
constexpr int K       = 8192;
constexpr int N       = 28672;
constexpr int KTILE   = 128;             // = group size: one scale per iter
constexpr int NTILE   = 128;             // per block
constexpr int THREADS = 128;             // 4 warps x 32 cols
constexpr int NITER   = K / KTILE;       // 64
constexpr int KSPLIT  = 4;
constexpr int NITER_S = NITER / KSPLIT;  // 16
constexpr int NBLK    = N / NTILE;       // 224
constexpr int SAS     = (KTILE + 8) * 2; // prep smem row stride (bytes)
constexpr int AIT     = 512;             // uint4 per iter in g_apack (8KB)
constexpr int WIT     = 512;             // uint4 weights per iter per block (8KB)

// A fragments: [iter][kk][mt*2+h][lane] as uint4 (4 mma regs)
__device__ uint4  g_apack[NITER * AIT];                  // 512 KB
__device__ float4 g_part4[KSPLIT * M * N / 4];           // split-K partials
__device__ int    g_cnt[NBLK];                           // arrival counters (zero-init)

__device__ __forceinline__ void ldmatrix_x4(uint32_t (&a)[4], const void* p) {
    uint32_t addr = (uint32_t)__cvta_generic_to_shared(p);
    asm volatile("ldmatrix.sync.aligned.m8n8.x4.shared.b16 {%0,%1,%2,%3}, [%4];"
                 : "=r"(a[0]), "=r"(a[1]), "=r"(a[2]), "=r"(a[3])
                 : "r"(addr));
}

__device__ __forceinline__ void mma16816(float (&d)[4], const uint4& av,
                                         uint32_t b0, uint32_t b1) {
    asm volatile(
        "mma.sync.aligned.m16n8k16.row.col.f32.f16.f16.f32 "
        "{%0,%1,%2,%3}, {%4,%5,%6,%7}, {%8,%9}, {%0,%1,%2,%3};"
        : "+f"(d[0]), "+f"(d[1]), "+f"(d[2]), "+f"(d[3])
        : "r"(av.x), "r"(av.y), "r"(av.z), "r"(av.w), "r"(b0), "r"(b1));
}

// Exact dequant, nibble pair at bits (0..3, 16..19): (q-8)*s.
__device__ __forceinline__ uint32_t deq_lo(uint32_t v, __half2 h1032, __half2 s2) {
    uint32_t q = (v & 0x000F000Fu) | 0x64006400u;   // 1024+q exact
    __half2 h = *reinterpret_cast<__half2*>(&q);
    __half2 r = __hmul2(__hsub2(h, h1032), s2);     // (q-8) exact, then 1 rounding
    return *reinterpret_cast<uint32_t*>(&r);
}
// Exact dequant, nibble pair at bits (4..7, 20..23), in place:
__device__ __forceinline__ uint32_t deq_hi(uint32_t v, __half2 h72, __half2 s2) {
    uint32_t q = (v & 0x00F000F0u) | 0x54005400u;   // 64+q exact
    __half2 h = *reinterpret_cast<__half2*>(&q);
    __half2 r = __hmul2(__hsub2(h, h72), s2);
    return *reinterpret_cast<uint32_t*>(&r);
}

__device__ __forceinline__ uint32_t pack_h2(float a, float b) {
    __half2 h = __floats2half2_rn(a, b);
    return *reinterpret_cast<uint32_t*>(&h);
}

__device__ __forceinline__ void cp_async16(void* smem_dst, const void* gsrc) {
    uint32_t s = (uint32_t)__cvta_generic_to_shared(smem_dst);
    asm volatile("cp.async.cg.shared.global [%0], [%1], 16;" :: "r"(s), "l"(gsrc));
}
#define CP_COMMIT() asm volatile("cp.async.commit_group;" ::: "memory")
#define CP_WAIT0()  asm volatile("cp.async.wait_group 0;" ::: "memory")

// ---------------- prep: x -> packed A fragments ----------------
__global__ void __launch_bounds__(THREADS)
prep_a(const float* __restrict__ x)
{
    __shared__ __align__(16) uint8_t sA[M * SAS];

    const int tid  = threadIdx.x;
    const int warp = tid >> 5;
    const int lane = tid & 31;
    const int it   = blockIdx.x;       // 0..63
    const int k0   = it * KTILE;

    const int xm  = tid >> 2;          // row 0..31
    const int xwb = (tid & 3) * 4;     // word-span base

    float4 xr[4][2];
    #pragma unroll
    for (int j = 0; j < 4; j++) {
        const float* xp = x + (size_t)xm * K + k0 + (xwb + j) * 8;
        xr[j][0] = *reinterpret_cast<const float4*>(xp);
        xr[j][1] = *reinterpret_cast<const float4*>(xp + 4);
    }
    #pragma unroll
    for (int j = 0; j < 4; j++) {
        const int wsp = xwb + j;
        uint32_t p0 = pack_h2(xr[j][0].x, xr[j][1].x);
        uint32_t p1 = pack_h2(xr[j][0].y, xr[j][1].y);
        uint32_t p2 = pack_h2(xr[j][0].z, xr[j][1].z);
        uint32_t p3 = pack_h2(xr[j][0].w, xr[j][1].w);
        uint8_t* base = sA + xm * SAS + (wsp >> 2) * 64 + (wsp & 3) * 4;
        *reinterpret_cast<uint32_t*>(base +  0) = p0;
        *reinterpret_cast<uint32_t*>(base + 16) = p1;
        *reinterpret_cast<uint32_t*>(base + 32) = p2;
        *reinterpret_cast<uint32_t*>(base + 48) = p3;
    }
    __syncthreads();

    const int lm_row = (lane & 15);
    const int lm_hi  = (lane & 16) ? 16 : 0;
    const int kk     = warp;           // one k32 chunk per warp

    #pragma unroll
    for (int mt = 0; mt < 2; mt++)
        #pragma unroll
        for (int h = 0; h < 2; h++) {
            uint32_t a[4];
            ldmatrix_x4(a, sA + (mt * 16 + lm_row) * SAS + kk * 64 + h * 32 + lm_hi);
            const int f = (it * 4 + kk) * 4 + mt * 2 + h;
            g_apack[f * 32 + lane] = make_uint4(a[0], a[1], a[2], a[3]);
        }
}

// ---------------- fused GEMM + split-K reduction ----------------
// stage A fragments: 8KB -> sAf[b]; 4 cp.async16 per thread
#define STAGE_A(b, itv)                                                        \
    do {                                                                       \
        const uint4* src_ = g_apack + (size_t)(itv) * AIT + tid;               \
        uint4* dst_ = &sAf[b][tid];                                            \
        _Pragma("unroll")                                                      \
        for (int j_ = 0; j_ < 4; j_++)                                         \
            cp_async16(dst_ + j_ * 128, src_ + j_ * 128);                      \
    } while (0)

// stage weights in FRAGMENT order: slot = kk*128 + w*32 + lane,
// src = qw[(it*16 + kk*4 + t) * N + nb0 + w*32 + 4c];  4 per thread.
// Consume: warp w reads sWf[b][kk*128 + w*32 + lane] as uint4 (4 phys cols).
#define STAGE_W(b, itv)                                                        \
    do {                                                                       \
        _Pragma("unroll")                                                      \
        for (int j_ = 0; j_ < 4; j_++) {                                       \
            const int slot_ = tid + j_ * 128;                                  \
            const int kk_   = slot_ >> 7;                                      \
            const int l_    = slot_ & 127;                                     \
            const int w_    = l_ >> 5;                                         \
            const int ln_   = l_ & 31;                                         \
            const int c_    = ln_ >> 2;                                        \
            const int t_    = ln_ & 3;                                         \
            cp_async16(&sWf[b][slot_],                                         \
                       qw + (size_t)((itv) * 16 + kk_ * 4 + t_) * N            \
                          + nb0 + w_ * 32 + 4 * c_);                           \
        }                                                                      \
    } while (0)

#define LOADS(dst, itv)                                                        \
    (dst) = *reinterpret_cast<const float4*>(scales + (size_t)(itv) * N + nc0)

__global__ void __launch_bounds__(THREADS, 7)
qlinear_fused(const uint32_t* __restrict__ qw,
              const float* __restrict__ scales,
              const float* __restrict__ bias,
              float* __restrict__ out)
{
    __shared__ __align__(16) uint4 sAf[2][AIT];   // 2 x 8KB
    __shared__ __align__(16) uint4 sWf[2][WIT];   // 2 x 8KB  (total 32KB)

    const int tid  = threadIdx.x;
    const int warp = tid >> 5;
    const int lane = tid & 31;
    const int nb0  = blockIdx.x * NTILE;
    const int nb   = nb0 + warp * 32;
    const int split = blockIdx.y;
    const int it0  = split * NITER_S;
    const int c    = lane >> 2;
    const int t    = lane & 3;
    const int nc0  = nb + 4 * c;

    const __half2 h1032 = __half2half2(__ushort_as_half((unsigned short)0x6408)); // 1032
    const __half2 h72   = __half2half2(__ushort_as_half((unsigned short)0x5480)); // 72

    float acc[2][4][4];
    #pragma unroll
    for (int i = 0; i < 2; i++)
        #pragma unroll
        for (int j = 0; j < 4; j++)
            #pragma unroll
            for (int l = 0; l < 4; l++) acc[i][j][l] = 0.0f;

    float4 sb0, sb1;
    STAGE_A(0, it0);
    STAGE_W(0, it0);
    CP_COMMIT();
    LOADS(sb0, it0);

    // STEP(i): wait stage(i), barrier, kick stage(i+1), compute(i).
    // The wait+barrier at STEP(i+1) entry guarantees all warps finished reading
    // buffers(i) before STEP(i+2)'s stage overwrites them.
    #define STEP(SCUR, SNXT, I, BUF)                                           \
    do {                                                                       \
        const int it_ = it0 + (I);                                             \
        CP_WAIT0();                                                            \
        __syncthreads();                                                       \
        if ((I) + 1 < NITER_S) {                                               \
            STAGE_A((BUF) ^ 1, it_ + 1);                                       \
            STAGE_W((BUF) ^ 1, it_ + 1);                                       \
            CP_COMMIT();                                                       \
            LOADS(SNXT, it_ + 1);                                              \
        }                                                                      \
        __half2 s2[4];                                                         \
        _Pragma("unroll")                                                      \
        for (int nt = 0; nt < 4; nt++)                                         \
            s2[nt] = __half2half2(__float2half_rn((&(SCUR).x)[nt]));           \
        _Pragma("unroll")                                                      \
        for (int kk = 0; kk < 4; kk++) {                                       \
            const uint4* sp = &sAf[BUF][kk * 128 + lane];                      \
            uint4 a0 = sp[0];    /* mt0 h0 */                                  \
            uint4 a1 = sp[32];   /* mt0 h1 */                                  \
            uint4 a2 = sp[64];   /* mt1 h0 */                                  \
            uint4 a3 = sp[96];   /* mt1 h1 */                                  \
            const uint4 ww4 = sWf[BUF][kk * 128 + warp * 32 + lane];           \
            _Pragma("unroll")                                                  \
            for (int nt = 0; nt < 4; nt++) {                                   \
                const uint32_t ww = (&ww4.x)[nt];                              \
                const uint32_t w8 = ww >> 8;                                   \
                uint32_t b00 = deq_lo(ww, h1032, s2[nt]);   /* q0,q4 */        \
                uint32_t b01 = deq_hi(ww, h72,   s2[nt]);   /* q1,q5 */        \
                uint32_t b10 = deq_lo(w8, h1032, s2[nt]);   /* q2,q6 */        \
                uint32_t b11 = deq_hi(w8, h72,   s2[nt]);   /* q3,q7 */        \
                mma16816(acc[0][nt], a0, b00, b01);                            \
                mma16816(acc[1][nt], a2, b00, b01);                            \
                mma16816(acc[0][nt], a1, b10, b11);                            \
                mma16816(acc[1][nt], a3, b10, b11);                            \
            }                                                                  \
        }                                                                      \
    } while (0)

    for (int i = 0; i < NITER_S; i += 2) {
        STEP(sb0, sb1, i,     0);
        STEP(sb1, sb0, i + 1, 1);
    }
    #undef STEP

    // -- write this split's partial (fp32, virtual column layout) --
    float* pp = reinterpret_cast<float*>(g_part4) + (size_t)split * M * N;
    #pragma unroll
    for (int mt = 0; mt < 2; mt++)
        #pragma unroll
        for (int nt = 0; nt < 4; nt++) {
            const int n  = nb + nt * 8 + t * 2;
            const int m0 = mt * 16 + c;
            *reinterpret_cast<float2*>(pp + (size_t)m0 * N + n) =
                make_float2(acc[mt][nt][0], acc[mt][nt][1]);
            *reinterpret_cast<float2*>(pp + (size_t)(m0 + 8) * N + n) =
                make_float2(acc[mt][nt][2], acc[mt][nt][3]);
        }

    // -- arrival counter: last split of this column-block reduces --
    // sLast aliases sAf[0][0] (dead after the final barrier+compute).
    int* sLast = reinterpret_cast<int*>(&sAf[0][0]);
    __threadfence();
    if (tid == 0) {
        int prev = atomicAdd(&g_cnt[blockIdx.x], 1);
        *sLast = (prev == KSPLIT - 1);
        if (prev == KSPLIT - 1) g_cnt[blockIdx.x] = 0;   // reset for next replay
    }
    __syncthreads();
    if (!*sLast) return;
    __threadfence();

    // out[m][phys] = bias + sum_s part[s][m][virt], fixed order (deterministic).
    // per 32-col group: phys q = 4*cv + nt  <->  virt v = nt*8 + cv
    const float* part = reinterpret_cast<const float*>(g_part4);
    #pragma unroll
    for (int e4 = tid; e4 < M * NTILE / 4; e4 += THREADS) {
        const int m = e4 >> 5;          // 32 float4 per 128-col row-tile
        const int k = e4 & 31;          // phys float4 index in row-tile
        float4 bv = *reinterpret_cast<const float4*>(bias + nb0 + 4 * k);
        float4 o4;
        #pragma unroll
        for (int j = 0; j < 4; j++) {
            const int virt = ((k >> 3) << 5) + j * 8 + (k & 7);
            const size_t pi = (size_t)m * N + nb0 + virt;
            float v = (&bv.x)[j];
            #pragma unroll
            for (int s = 0; s < KSPLIT; s++)
                v += part[(size_t)s * M * N + pi];
            (&o4.x)[j] = v;
        }
        *reinterpret_cast<float4*>(out + (size_t)m * N + nb0 + 4 * k) = o4;
    }
}

} // namespace

extern "C" void kernel_launch(void* const* d_in, const int* in_sizes, int n_in,
                              void* d_out, int out_size)
{
    const float*    x  = (const float*)d_in[0];
    const uint32_t* qw = (const uint32_t*)d_in[1];
    const float*    sc = (const float*)d_in[2];
    const float*    bs = (const float*)d_in[3];
    float*          o  = (float*)d_out;

    prep_a<<<NITER, THREADS>>>(x);                                 // 64 blocks
    qlinear_fused<<<dim3(NBLK, KSPLIT), THREADS>>>(qw, sc, bs, o); // 224 x 4
}

// round 15
// speedup vs baseline: 1.1314x; 1.1314x over previous
#include <cuda_runtime.h>
#include <cuda_fp16.h>
#include <stdint.h>

// W4A16 grouped-dequant GEMM:  out[32, 28672] = x[32, 8192] @ dequant(qweight) + bias
// All fp16 tensors are promoted to float32 by the harness (x, scales, bias, out).
//
// R15: tcgen05 unavailable (harness compiles via compute_103 PTX -> no 'a'
// features). mma.sync path, attacking warp co-stall:
//   - 3-deep cp.async pipeline for the A-fragment tiles (wait_group 1)
//   - 256 threads / NTILE=256: A staging + barriers amortized over 8 warps
//   - weights + scales register-prefetched 1 iter ahead (direct LDG, streamed)
//   - fused split-K (KSPLIT=4) with counter + last-block reduction

namespace {

constexpr int M       = 32;
constexpr int K       = 8192;
constexpr int N       = 28672;
constexpr int NTILE   = 256;              // per block
constexpr int THREADS = 256;              // 8 warps x 32 cols
constexpr int THR_P   = 128;              // prep kernel threads
constexpr int NITER   = K / 128;          // 64 k-tiles (= group size)
constexpr int KSPLIT  = 4;
constexpr int NITER_S = NITER / KSPLIT;   // 16
constexpr int NBLK    = N / NTILE;        // 112
constexpr int SAS     = (128 + 8) * 2;    // prep smem row stride (bytes)
constexpr int AIT     = 512;              // uint4 per iter in g_apack (8KB)

// A fragments: [iter][kk][mt*2+h][lane] as uint4 (4 mma regs)
__device__ uint4  g_apack[NITER * AIT];                  // 512 KB
__device__ float4 g_part4[KSPLIT * M * N / 4];           // split-K partials
__device__ int    g_cnt[NBLK];                           // arrival counters (zero-init)

__device__ __forceinline__ void ldmatrix_x4(uint32_t (&a)[4], const void* p) {
    uint32_t addr = (uint32_t)__cvta_generic_to_shared(p);
    asm volatile("ldmatrix.sync.aligned.m8n8.x4.shared.b16 {%0,%1,%2,%3}, [%4];"
                 : "=r"(a[0]), "=r"(a[1]), "=r"(a[2]), "=r"(a[3])
                 : "r"(addr));
}

__device__ __forceinline__ void mma16816(float (&d)[4], const uint4& av,
                                         uint32_t b0, uint32_t b1) {
    asm volatile(
        "mma.sync.aligned.m16n8k16.row.col.f32.f16.f16.f32 "
        "{%0,%1,%2,%3}, {%4,%5,%6,%7}, {%8,%9}, {%0,%1,%2,%3};"
        : "+f"(d[0]), "+f"(d[1]), "+f"(d[2]), "+f"(d[3])
        : "r"(av.x), "r"(av.y), "r"(av.z), "r"(av.w), "r"(b0), "r"(b1));
}

// Exact dequant, nibble pair at bits (0..3, 16..19): (q-8)*s.
__device__ __forceinline__ uint32_t deq_lo(uint32_t v, __half2 h1032, __half2 s2) {
    uint32_t q = (v & 0x000F000Fu) | 0x64006400u;   // 1024+q exact
    __half2 h = *reinterpret_cast<__half2*>(&q);
    __half2 r = __hmul2(__hsub2(h, h1032), s2);     // (q-8) exact, then 1 rounding
    return *reinterpret_cast<uint32_t*>(&r);
}
// Exact dequant, nibble pair at bits (4..7, 20..23), in place:
__device__ __forceinline__ uint32_t deq_hi(uint32_t v, __half2 h72, __half2 s2) {
    uint32_t q = (v & 0x00F000F0u) | 0x54005400u;   // 64+q exact
    __half2 h = *reinterpret_cast<__half2*>(&q);
    __half2 r = __hmul2(__hsub2(h, h72), s2);
    return *reinterpret_cast<uint32_t*>(&r);
}

__device__ __forceinline__ uint32_t pack_h2(float a, float b) {
    __half2 h = __floats2half2_rn(a, b);
    return *reinterpret_cast<uint32_t*>(&h);
}

__device__ __forceinline__ void cp_async16(void* smem_dst, const void* gsrc) {
    uint32_t s = (uint32_t)__cvta_generic_to_shared(smem_dst);
    asm volatile("cp.async.cg.shared.global [%0], [%1], 16;" :: "r"(s), "l"(gsrc));
}
#define CP_COMMIT() asm volatile("cp.async.commit_group;" ::: "memory")
#define CP_WAIT0()  asm volatile("cp.async.wait_group 0;" ::: "memory")
#define CP_WAIT1()  asm volatile("cp.async.wait_group 1;" ::: "memory")

__device__ __forceinline__ uint4 ldcs4(const uint32_t* p) {
    uint4 v;
    asm volatile("ld.global.cs.v4.u32 {%0,%1,%2,%3}, [%4];"
                 : "=r"(v.x), "=r"(v.y), "=r"(v.z), "=r"(v.w) : "l"(p));
    return v;
}

// ---------------- prep: x -> packed A fragments ----------------
__global__ void __launch_bounds__(THR_P)
prep_a(const float* __restrict__ x)
{
    __shared__ __align__(16) uint8_t sA[M * SAS];

    const int tid  = threadIdx.x;
    const int warp = tid >> 5;
    const int lane = tid & 31;
    const int it   = blockIdx.x;       // 0..63
    const int k0   = it * 128;

    const int xm  = tid >> 2;          // row 0..31
    const int xwb = (tid & 3) * 4;     // word-span base

    float4 xr[4][2];
    #pragma unroll
    for (int j = 0; j < 4; j++) {
        const float* xp = x + (size_t)xm * K + k0 + (xwb + j) * 8;
        xr[j][0] = *reinterpret_cast<const float4*>(xp);
        xr[j][1] = *reinterpret_cast<const float4*>(xp + 4);
    }
    #pragma unroll
    for (int j = 0; j < 4; j++) {
        const int wsp = xwb + j;
        uint32_t p0 = pack_h2(xr[j][0].x, xr[j][1].x);
        uint32_t p1 = pack_h2(xr[j][0].y, xr[j][1].y);
        uint32_t p2 = pack_h2(xr[j][0].z, xr[j][1].z);
        uint32_t p3 = pack_h2(xr[j][0].w, xr[j][1].w);
        uint8_t* base = sA + xm * SAS + (wsp >> 2) * 64 + (wsp & 3) * 4;
        *reinterpret_cast<uint32_t*>(base +  0) = p0;
        *reinterpret_cast<uint32_t*>(base + 16) = p1;
        *reinterpret_cast<uint32_t*>(base + 32) = p2;
        *reinterpret_cast<uint32_t*>(base + 48) = p3;
    }
    __syncthreads();

    const int lm_row = (lane & 15);
    const int lm_hi  = (lane & 16) ? 16 : 0;
    const int kk     = warp;           // one k32 chunk per warp

    #pragma unroll
    for (int mt = 0; mt < 2; mt++)
        #pragma unroll
        for (int h = 0; h < 2; h++) {
            uint32_t a[4];
            ldmatrix_x4(a, sA + (mt * 16 + lm_row) * SAS + kk * 64 + h * 32 + lm_hi);
            const int f = (it * 4 + kk) * 4 + mt * 2 + h;
            g_apack[f * 32 + lane] = make_uint4(a[0], a[1], a[2], a[3]);
        }
}

// ---------------- fused GEMM + split-K reduction ----------------
// weights: 4 x uint4 per thread per iter, direct streamed LDG
#define LOADW(buf, itv)                                                        \
    do {                                                                       \
        const int krow0_ = (itv) * 16;                                         \
        _Pragma("unroll")                                                      \
        for (int kk_ = 0; kk_ < 4; kk_++)                                      \
            (buf)[kk_] = ldcs4(qw + (size_t)(krow0_ + kk_ * 4 + t) * N + nc0); \
    } while (0)

#define LOADS(dst, itv)                                                        \
    (dst) = *reinterpret_cast<const float4*>(scales + (size_t)(itv) * N + nc0)

// stage iter itv's 8KB A block into smem buffer b (256 threads -> 2 cp each)
#define STAGE_A(b, itv)                                                        \
    do {                                                                       \
        const uint4* src_ = g_apack + (size_t)(itv) * AIT + tid;               \
        uint4* dst_ = &sAf[b][tid];                                            \
        cp_async16(dst_,       src_);                                          \
        cp_async16(dst_ + 256, src_ + 256);                                    \
        CP_COMMIT();                                                           \
    } while (0)

__global__ void __launch_bounds__(THREADS, 3)
qlinear_fused(const uint32_t* __restrict__ qw,
              const float* __restrict__ scales,
              const float* __restrict__ bias,
              float* __restrict__ out)
{
    __shared__ __align__(16) uint4 sAf[3][AIT];   // 3 x 8KB
    __shared__ int sLast;

    const int tid  = threadIdx.x;
    const int warp = tid >> 5;                    // 0..7
    const int lane = tid & 31;
    const int nb0  = blockIdx.x * NTILE;
    const int nb   = nb0 + warp * 32;
    const int split = blockIdx.y;
    const int it0  = split * NITER_S;
    const int c    = lane >> 2;
    const int t    = lane & 3;
    const int nc0  = nb + 4 * c;

    const __half2 h1032 = __half2half2(__ushort_as_half((unsigned short)0x6408)); // 1032
    const __half2 h72   = __half2half2(__ushort_as_half((unsigned short)0x5480)); // 72

    float acc[2][4][4];
    #pragma unroll
    for (int i = 0; i < 2; i++)
        #pragma unroll
        for (int j = 0; j < 4; j++)
            #pragma unroll
            for (int l = 0; l < 4; l++) acc[i][j][l] = 0.0f;

    uint4 wb0[4], wb1[4];
    float4 sb0, sb1;
    // prolog: stages 0 and 1 in flight, weights/scales for iter 0 in regs
    STAGE_A(0, it0);
    STAGE_A(1, it0 + 1);
    LOADW(wb0, it0);
    LOADS(sb0, it0);

    // STEP(i): wait for stage(i) (wait_group 1: only stage(i+1) may be pending;
    // final iter uses wait 0), barrier, kick stage(i+2) into buf (i+2)%3 (that
    // buffer held stage(i-1), which every warp finished before this barrier),
    // prefetch weights/scales(i+1), compute(i).
    #define STEP(WCUR, WNXT, SCUR, SNXT, I, BUF)                               \
    do {                                                                       \
        const int it_ = it0 + (I);                                             \
        if ((I) < NITER_S - 1) { CP_WAIT1(); } else { CP_WAIT0(); }            \
        __syncthreads();                                                       \
        if ((I) + 2 < NITER_S) STAGE_A(((BUF) + 2) % 3, it_ + 2);              \
        if ((I) + 1 < NITER_S) { LOADW(WNXT, it_ + 1); LOADS(SNXT, it_ + 1); } \
        __half2 s2[4];                                                         \
        _Pragma("unroll")                                                      \
        for (int nt = 0; nt < 4; nt++)                                         \
            s2[nt] = __half2half2(__float2half_rn((&(SCUR).x)[nt]));           \
        _Pragma("unroll")                                                      \
        for (int kk = 0; kk < 4; kk++) {                                       \
            const uint4* sp = &sAf[BUF][kk * 128 + lane];                      \
            uint4 a0 = sp[0];    /* mt0 h0 */                                  \
            uint4 a1 = sp[32];   /* mt0 h1 */                                  \
            uint4 a2 = sp[64];   /* mt1 h0 */                                  \
            uint4 a3 = sp[96];   /* mt1 h1 */                                  \
            const uint4 ww4 = (WCUR)[kk];                                      \
            _Pragma("unroll")                                                  \
            for (int nt = 0; nt < 4; nt++) {                                   \
                const uint32_t ww = (&ww4.x)[nt];                              \
                const uint32_t w8 = ww >> 8;                                   \
                uint32_t b00 = deq_lo(ww, h1032, s2[nt]);   /* q0,q4 */        \
                uint32_t b01 = deq_hi(ww, h72,   s2[nt]);   /* q1,q5 */        \
                uint32_t b10 = deq_lo(w8, h1032, s2[nt]);   /* q2,q6 */        \
                uint32_t b11 = deq_hi(w8, h72,   s2[nt]);   /* q3,q7 */        \
                mma16816(acc[0][nt], a0, b00, b01);                            \
                mma16816(acc[1][nt], a2, b00, b01);                            \
                mma16816(acc[0][nt], a1, b10, b11);                            \
                mma16816(acc[1][nt], a3, b10, b11);                            \
            }                                                                  \
        }                                                                      \
    } while (0)

    // NITER_S = 16; buffer of iter i is i%3 -> 6-iter macro period, 16 = 2*6+4
    for (int i = 0; i < 12; i += 6) {
        STEP(wb0, wb1, sb0, sb1, i + 0, 0);
        STEP(wb1, wb0, sb1, sb0, i + 1, 1);
        STEP(wb0, wb1, sb0, sb1, i + 2, 2);
        STEP(wb1, wb0, sb1, sb0, i + 3, 0);
        STEP(wb0, wb1, sb0, sb1, i + 4, 1);
        STEP(wb1, wb0, sb1, sb0, i + 5, 2);
    }
    STEP(wb0, wb1, sb0, sb1, 12, 0);
    STEP(wb1, wb0, sb1, sb0, 13, 1);
    STEP(wb0, wb1, sb0, sb1, 14, 2);
    STEP(wb1, wb0, sb1, sb0, 15, 0);
    #undef STEP

    // -- write this split's partial (fp32, virtual column layout) --
    float* pp = reinterpret_cast<float*>(g_part4) + (size_t)split * M * N;
    #pragma unroll
    for (int mt = 0; mt < 2; mt++)
        #pragma unroll
        for (int nt = 0; nt < 4; nt++) {
            const int n  = nb + nt * 8 + t * 2;
            const int m0 = mt * 16 + c;
            *reinterpret_cast<float2*>(pp + (size_t)m0 * N + n) =
                make_float2(acc[mt][nt][0], acc[mt][nt][1]);
            *reinterpret_cast<float2*>(pp + (size_t)(m0 + 8) * N + n) =
                make_float2(acc[mt][nt][2], acc[mt][nt][3]);
        }

    // -- arrival counter: last split of this column-block reduces --
    __threadfence();
    if (tid == 0) {
        int prev = atomicAdd(&g_cnt[blockIdx.x], 1);
        sLast = (prev == KSPLIT - 1);
        if (prev == KSPLIT - 1) g_cnt[blockIdx.x] = 0;   // reset for next replay
    }
    __syncthreads();
    if (!sLast) return;
    __threadfence();

    // out[m][phys] = bias + sum_s part[s][m][virt], fixed order (deterministic).
    // per 32-col group: phys q = 4*cv + nt  <->  virt v = nt*8 + cv
    const float* part = reinterpret_cast<const float*>(g_part4);
    #pragma unroll
    for (int e4 = tid; e4 < M * NTILE / 4; e4 += THREADS) {
        const int m = e4 >> 6;          // 64 float4 per 256-col row-tile
        const int k = e4 & 63;          // phys float4 index in row-tile
        float4 bv = *reinterpret_cast<const float4*>(bias + nb0 + 4 * k);
        float4 o4;
        #pragma unroll
        for (int j = 0; j < 4; j++) {
            const int virt = ((k >> 3) << 5) + j * 8 + (k & 7);
            const size_t pi = (size_t)m * N + nb0 + virt;
            float v = (&bv.x)[j];
            #pragma unroll
            for (int s = 0; s < KSPLIT; s++)
                v += part[(size_t)s * M * N + pi];
            (&o4.x)[j] = v;
        }
        *reinterpret_cast<float4*>(out + (size_t)m * N + nb0 + 4 * k) = o4;
    }
}

} // namespace

extern "C" void kernel_launch(void* const* d_in, const int* in_sizes, int n_in,
                              void* d_out, int out_size)
{
    const float*    x  = (const float*)d_in[0];
    const uint32_t* qw = (const uint32_t*)d_in[1];
    const float*    sc = (const float*)d_in[2];
    const float*    bs = (const float*)d_in[3];
    float*          o  = (float*)d_out;

    prep_a<<<NITER, THR_P>>>(x);                                   // 64 blocks
    qlinear_fused<<<dim3(NBLK, KSPLIT), THREADS>>>(qw, sc, bs, o); // 112 x 4
}